// round 7
// baseline (speedup 1.0000x reference)
#include <cuda_runtime.h>
#include <cuda_fp16.h>
#include <stdint.h>

// RayCastLayer as a split-fp16 GEMM on the classic tensor-core path
// (ldmatrix + mma.sync.m16n8k16 — the sm_100 non-'a' target has no tcgen05).
//
//   out[2048 x 361] = x[2048 x 361] * M[361 x 361]
//
// M is the data-independent ray operator (symmetric), built from `weight`.
// Precision: x = xhi + xlo, M = Mhi + Mlo (fp16 splits);
//   out ~= xhi*Mhi + xlo*Mhi + xhi*Mlo   (lo*lo dropped, ~2^-22)
// The three terms share fragments: per k16 we load Ahi/Alo/Bhi/Blo frags once
// and issue 3 MMAs. K padded to 384. B stored [n][k] (symmetric M) so all
// ldmatrix ops are non-transposed.

#define BOARD 19
#define NPOS  361
#define KP    384               // padded K
#define LDK   768               // g_A / g_B row pitch in halves: [hi 384 | lo 384]
#define MT    64
#define NT    64
#define KC    32                // k per pipeline chunk
#define NCH   12                // 384 / 32
#define SPITCH 72               // smem row pitch in halves (144 B) -> ldmatrix conflict-free

__device__ __align__(16) __half g_A[2048 * LDK];   // [m][ xhi(384) | xlo(384) ]
__device__ __align__(16) __half g_B[KP * LDK];     // [n][ Mhi(384) | Mlo(384) ]

// ---------------- prep kernels ----------------------------------------------

__global__ void prep_x(const float* __restrict__ x, int nplanes) {
    int id = blockIdx.x * blockDim.x + threadIdx.x;
    if (id >= nplanes * KP) return;
    int m = id / KP, q = id - m * KP;
    float v = (q < NPOS) ? x[m * NPOS + q] : 0.f;
    __half h = __float2half_rn(v);
    __half l = __float2half_rn(v - __half2float(h));
    g_A[m * LDK + q]      = h;
    g_A[m * LDK + KP + q] = l;
}

__global__ void prep_B(const float* __restrict__ w) {
    int id = blockIdx.x * blockDim.x + threadIdx.x;
    if (id >= KP * KP) return;
    int n = id / KP, q = id - n * KP;
    float val = 0.f;
    if (n < NPOS && q < NPOS) {
        int yn = n / BOARD, xn = n - yn * BOARD;
        int yq = q / BOARD, xq = q - yq * BOARD;
        int dy = yq - yn, dx = xq - xn;
        int ady = dy < 0 ? -dy : dy, adx = dx < 0 ? -dx : dx;
        if (!(dy == 0 && dx == 0)) {
            if      (dx == 0)    val = w[ady - 1];        // vertical line
            else if (dy == 0)    val = w[adx - 1];        // horizontal line
            else if (ady == adx) val = w[18 + ady - 1];   // exact diagonal
        }
    }
    __half h = __float2half_rn(val);
    __half l = __float2half_rn(val - __half2float(h));
    g_B[n * LDK + q]      = h;
    g_B[n * LDK + KP + q] = l;
}

// ---------------- GEMM -------------------------------------------------------

__device__ __forceinline__ void ldmx4(uint32_t* r, uint32_t addr) {
    asm volatile("ldmatrix.sync.aligned.m8n8.x4.shared.b16 {%0,%1,%2,%3}, [%4];"
                 : "=r"(r[0]), "=r"(r[1]), "=r"(r[2]), "=r"(r[3]) : "r"(addr));
}

__device__ __forceinline__ void mma16816(float* d, const uint32_t* a, const uint32_t* b) {
    asm volatile("mma.sync.aligned.m16n8k16.row.col.f32.f16.f16.f32 "
                 "{%0,%1,%2,%3}, {%4,%5,%6,%7}, {%8,%9}, {%0,%1,%2,%3};"
                 : "+f"(d[0]), "+f"(d[1]), "+f"(d[2]), "+f"(d[3])
                 : "r"(a[0]), "r"(a[1]), "r"(a[2]), "r"(a[3]), "r"(b[0]), "r"(b[1]));
}

// Load one chunk: A rows [m0,m0+64) and B rows [n0,n0+64), k cols
// [kc*32, kc*32+32) of BOTH hi and lo segments. 1024 16B granules, 128 threads.
__device__ __forceinline__ void load_chunk(uint32_t sa, uint32_t sb,
                                           int m0, int n0, int kc, int tid) {
    #pragma unroll
    for (int i = 0; i < 8; i++) {
        int id  = tid + i * 128;        // 0..1023
        int isB = id >> 9;
        int l   = id & 511;
        int r   = l >> 3;               // row 0..63
        int g   = l & 7;                // granule 0..7
        int seg = g >> 2;               // 0 = hi, 1 = lo
        int t   = g & 3;                // 16B granule within 32 halves
        const __half* src = (isB ? g_B + (n0 + r) * LDK : g_A + (m0 + r) * LDK)
                            + seg * KP + kc * KC + t * 8;
        uint32_t dst = (isB ? sb : sa) + r * (SPITCH * 2) + seg * 64 + t * 16;
        asm volatile("cp.async.ca.shared.global [%0], [%1], 16;" :: "r"(dst), "l"(src));
    }
    asm volatile("cp.async.commit_group;" ::: "memory");
}

__global__ __launch_bounds__(128, 4)
void gemm_kernel(float* __restrict__ out, int nplanes)
{
    __shared__ __align__(16) __half stg[2][2][MT * SPITCH];  // [stage][A/B][...]

    const int tid  = threadIdx.x;
    const int lane = tid & 31;
    const int wid  = tid >> 5;
    const int wm   = wid & 1;           // warp grid 2x2, warp tile 32x32
    const int wn   = wid >> 1;
    const int m0   = blockIdx.x * MT;
    const int n0   = blockIdx.y * NT;

    uint32_t sbase = (uint32_t)__cvta_generic_to_shared(&stg[0][0][0]);
    const uint32_t stageB = (uint32_t)(MT * SPITCH * 2);     // 9216 bytes
    uint32_t sa[2] = { sbase,              sbase + 2 * stageB };
    uint32_t sb[2] = { sbase + stageB,     sbase + 3 * stageB };

    // ldmatrix lane-address components (mat = lane>>3)
    const int mat = lane >> 3;
    const int mr  = lane & 7;
    // A: row = base + mf*16 + (mat&1)*8 + mr ; k-col += (mat>>1)*8
    const uint32_t aRow = (uint32_t)((wm * 32 + (mat & 1) * 8 + mr) * (SPITCH * 2));
    const uint32_t aKof = (uint32_t)((mat >> 1) * 8 * 2);
    // B: row = base + (p*2 + (mat>>1))*8 + mr ; k-col += (mat&1)*8
    const uint32_t bRow = (uint32_t)((wn * 32 + (mat >> 1) * 8 + mr) * (SPITCH * 2));
    const uint32_t bKof = (uint32_t)((mat & 1) * 8 * 2);

    float acc[2][4][4];
    #pragma unroll
    for (int i = 0; i < 2; i++)
        #pragma unroll
        for (int j = 0; j < 4; j++)
            #pragma unroll
            for (int k = 0; k < 4; k++) acc[i][j][k] = 0.f;

    load_chunk(sa[0], sb[0], m0, n0, 0, tid);

    for (int c = 0; c < NCH; c++) {
        if (c + 1 < NCH)
            load_chunk(sa[(c + 1) & 1], sb[(c + 1) & 1], m0, n0, c + 1, tid);
        if (c + 1 < NCH) asm volatile("cp.async.wait_group 1;" ::: "memory");
        else             asm volatile("cp.async.wait_group 0;" ::: "memory");
        __syncthreads();

        const uint32_t au = sa[c & 1];
        const uint32_t bu = sb[c & 1];

        #pragma unroll
        for (int s = 0; s < 2; s++) {                 // two k16 steps per chunk
            uint32_t ah[2][4], al[2][4], bh[4][2], bl[4][2];
            #pragma unroll
            for (int mf = 0; mf < 2; mf++) {
                uint32_t base = au + aRow + (uint32_t)(mf * 16 * (SPITCH * 2))
                              + (uint32_t)(s * 16 * 2) + aKof;
                ldmx4(ah[mf], base);          // hi: cols [s*16, s*16+16)
                ldmx4(al[mf], base + 64);     // lo: +32 halves
            }
            #pragma unroll
            for (int p = 0; p < 2; p++) {
                uint32_t base = bu + bRow + (uint32_t)(p * 16 * (SPITCH * 2))
                              + (uint32_t)(s * 16 * 2) + bKof;
                uint32_t rh[4], rl[4];
                ldmx4(rh, base);
                ldmx4(rl, base + 64);
                bh[p*2+0][0] = rh[0]; bh[p*2+0][1] = rh[1];
                bh[p*2+1][0] = rh[2]; bh[p*2+1][1] = rh[3];
                bl[p*2+0][0] = rl[0]; bl[p*2+0][1] = rl[1];
                bl[p*2+1][0] = rl[2]; bl[p*2+1][1] = rl[3];
            }
            #pragma unroll
            for (int mf = 0; mf < 2; mf++)
                #pragma unroll
                for (int nf = 0; nf < 4; nf++) {
                    mma16816(acc[mf][nf], ah[mf], bh[nf]);   // xhi * Mhi
                    mma16816(acc[mf][nf], al[mf], bh[nf]);   // xlo * Mhi
                    mma16816(acc[mf][nf], ah[mf], bl[nf]);   // xhi * Mlo
                }
        }
        __syncthreads();
    }

    // ---- epilogue: direct stores (each output owned by exactly one thread) ----
    const int g = lane >> 2;
    const int t = lane & 3;
    #pragma unroll
    for (int mf = 0; mf < 2; mf++) {
        #pragma unroll
        for (int nf = 0; nf < 4; nf++) {
            const int m = m0 + wm * 32 + mf * 16 + g;
            const int n = n0 + wn * 32 + nf * 8 + 2 * t;
            if (m < nplanes) {
                if (n     < NPOS) out[m * NPOS + n]     = acc[mf][nf][0];
                if (n + 1 < NPOS) out[m * NPOS + n + 1] = acc[mf][nf][1];
            }
            if (m + 8 < nplanes || (m + 8 < 2048 && m + 8 < nplanes + 8)) { /* fallthrough guard below */ }
            const int m2 = m + 8;
            if (m2 < nplanes) {
                if (n     < NPOS) out[m2 * NPOS + n]     = acc[mf][nf][2];
                if (n + 1 < NPOS) out[m2 * NPOS + n + 1] = acc[mf][nf][3];
            }
        }
    }
}

// ---------------- launch -----------------------------------------------------

extern "C" void kernel_launch(void* const* d_in, const int* in_sizes, int n_in,
                              void* d_out, int out_size)
{
    const float* x      = (const float*)d_in[0];   // [32,64,19,19]
    const float* weight = (const float*)d_in[1];   // [2,18]
    float* out          = (float*)d_out;

    const int nplanes = in_sizes[0] / NPOS;        // 2048

    prep_x<<<(nplanes * KP + 255) / 256, 256>>>(x, nplanes);
    prep_B<<<(KP * KP + 255) / 256, 256>>>(weight);

    dim3 grid((nplanes + MT - 1) / MT, (NPOS + NT - 1) / NT);   // 32 x 6
    gemm_kernel<<<grid, 128>>>(out, nplanes);
}

// round 8
// speedup vs baseline: 1.0898x; 1.0898x over previous
#include <cuda_runtime.h>
#include <cuda_fp16.h>
#include <stdint.h>

// RayCastLayer as a split-fp16 GEMM (classic mma.sync path; sm_100 has no tcgen05
// in this harness's ptxas target).
//   out[2048 x 361] = x[2048 x 361] * M[361 x 361]
// M = symmetric ray operator built from `weight` (prep_B).
// Split precision: out = xhi*Mhi + xlo*Mhi + xhi*Mlo  (lo*lo dropped, ~2^-22).
// A (x) is loaded DIRECTLY from fp32 global into mma fragments with in-register
// hi/lo fp16 split — no prep_x kernel, no fp16 copy of x in HBM.
// B lives in __device__ global (fp16 hi|lo per row), staged via cp.async +
// ldmatrix exactly as the verified R7 path.

#define BOARD 19
#define NPOS  361
#define KP    384               // padded K
#define LDK   768               // g_B row pitch in halves: [hi 384 | lo 384]
#define MT    32                // CTA tile M (planes)
#define NT    64                // CTA tile N (positions)
#define KC    32                // k per pipeline chunk
#define NCHK  12                // 384 / 32
#define SPITCH 72               // smem B row pitch in halves -> conflict-free ldmatrix

__device__ __align__(16) __half g_B[KP * LDK];     // [n][ Mhi(384) | Mlo(384) ]

// ---------------- prep kernel: build split operator matrix -------------------

__global__ void prep_B(const float* __restrict__ w) {
    int id = blockIdx.x * blockDim.x + threadIdx.x;
    if (id >= KP * (KP / 2)) return;
    int n  = id / (KP / 2);
    int qi = id - n * (KP / 2);
    uint32_t hw = 0, lw = 0;
    #pragma unroll
    for (int j = 0; j < 2; j++) {
        int q = qi * 2 + j;
        float val = 0.f;
        if (n < NPOS && q < NPOS) {
            int yn = n / BOARD, xn = n - yn * BOARD;
            int yq = q / BOARD, xq = q - yq * BOARD;
            int dy = yq - yn, dx = xq - xn;
            int ady = dy < 0 ? -dy : dy, adx = dx < 0 ? -dx : dx;
            if (!(dy == 0 && dx == 0)) {
                if      (dx == 0)    val = w[ady - 1];        // vertical
                else if (dy == 0)    val = w[adx - 1];        // horizontal
                else if (ady == adx) val = w[18 + ady - 1];   // diagonal
            }
        }
        __half h = __float2half_rn(val);
        __half l = __float2half_rn(val - __half2float(h));
        hw |= (uint32_t)__half_as_ushort(h) << (16 * j);
        lw |= (uint32_t)__half_as_ushort(l) << (16 * j);
    }
    uint32_t* B32 = reinterpret_cast<uint32_t*>(g_B);
    B32[n * (LDK / 2) + qi]            = hw;   // hi words [0,192)
    B32[n * (LDK / 2) + KP / 2 + qi]   = lw;   // lo words [192,384)
}

// ---------------- GEMM helpers ----------------------------------------------

__device__ __forceinline__ void ldmx4(uint32_t* r, uint32_t addr) {
    asm volatile("ldmatrix.sync.aligned.m8n8.x4.shared.b16 {%0,%1,%2,%3}, [%4];"
                 : "=r"(r[0]), "=r"(r[1]), "=r"(r[2]), "=r"(r[3]) : "r"(addr));
}

__device__ __forceinline__ void mma16816(float* d, const uint32_t* a, const uint32_t* b) {
    asm volatile("mma.sync.aligned.m16n8k16.row.col.f32.f16.f16.f32 "
                 "{%0,%1,%2,%3}, {%4,%5,%6,%7}, {%8,%9}, {%0,%1,%2,%3};"
                 : "+f"(d[0]), "+f"(d[1]), "+f"(d[2]), "+f"(d[3])
                 : "r"(a[0]), "r"(a[1]), "r"(a[2]), "r"(a[3]), "r"(b[0]), "r"(b[1]));
}

__device__ __forceinline__ void packsplit(float v0, float v1,
                                          uint32_t& h, uint32_t& l) {
    __half2 hh = __floats2half2_rn(v0, v1);
    float2 hf  = __half22float2(hh);
    __half2 ll = __floats2half2_rn(v0 - hf.x, v1 - hf.y);
    h = *reinterpret_cast<uint32_t*>(&hh);
    l = *reinterpret_cast<uint32_t*>(&ll);
}

// B chunk load: 64 rows x (32 hi + 32 lo) halves -> 512 16B granules, 128 thr.
__device__ __forceinline__ void loadB(uint32_t sb, int n0, int kb, int tid) {
    #pragma unroll
    for (int i = 0; i < 4; i++) {
        int id  = tid + i * 128;          // 0..511
        int r   = id >> 3;                // row 0..63
        int g   = id & 7;
        int seg = g >> 2;                 // 0 = hi, 1 = lo
        int t   = g & 3;
        const __half* src = g_B + (n0 + r) * LDK + seg * KP + kb + t * 8;
        uint32_t dst = sb + (uint32_t)(r * (SPITCH * 2) + seg * 64 + t * 16);
        asm volatile("cp.async.ca.shared.global [%0], [%1], 16;" :: "r"(dst), "l"(src));
    }
    asm volatile("cp.async.commit_group;" ::: "memory");
}

__global__ __launch_bounds__(128, 4)
void gemm_kernel(const float* __restrict__ x, float* __restrict__ out, int nplanes)
{
    __shared__ __align__(16) __half stg[2][NT * SPITCH];

    const int tid  = threadIdx.x;
    const int lane = tid & 31;
    const int wid  = tid >> 5;
    const int wm   = wid & 1;             // warp grid 2(m) x 2(n); warp tile 16 x 32
    const int wn   = wid >> 1;
    const int m0   = blockIdx.x * MT;
    const int n0   = blockIdx.y * NT;

    const int g  = lane >> 2;             // A-fragment row within 8
    const int t2 = (lane & 3) * 2;        // A-fragment k within 8

    uint32_t sbase = (uint32_t)__cvta_generic_to_shared(&stg[0][0]);
    const uint32_t stageB = (uint32_t)(NT * SPITCH * 2);
    const uint32_t sb[2] = { sbase, sbase + stageB };

    // B ldmatrix lane addressing (verified in R7):
    const int mat = lane >> 3;
    const int mr  = lane & 7;
    const uint32_t bRow = (uint32_t)((wn * 32 + (mat >> 1) * 8 + mr) * (SPITCH * 2));
    const uint32_t bKof = (uint32_t)((mat & 1) * 16);

    // A source rows for this thread (fixed): r0 = m0+wm*16+g, r1 = r0+8
    const float* xr0 = x + (size_t)(m0 + wm * 16 + g) * NPOS;
    const float* xr1 = xr0 + 8 * NPOS;

    float acc[4][4];
    #pragma unroll
    for (int i = 0; i < 4; i++)
        #pragma unroll
        for (int j = 0; j < 4; j++) acc[i][j] = 0.f;

    float av[2][16];

    // A register prefetch for chunk c into buffer b
    #define LOAD_A(b, c) do {                                                  \
        const int _kb = (c) * KC;                                              \
        _Pragma("unroll")                                                      \
        for (int s = 0; s < 2; s++) {                                          \
            const int qb = _kb + s * 16 + t2;                                  \
            av[b][s*8+0] = (qb     < NPOS) ? __ldg(xr0 + qb)     : 0.f;        \
            av[b][s*8+1] = (qb + 1 < NPOS) ? __ldg(xr0 + qb + 1) : 0.f;        \
            av[b][s*8+2] = (qb + 8 < NPOS) ? __ldg(xr0 + qb + 8) : 0.f;        \
            av[b][s*8+3] = (qb + 9 < NPOS) ? __ldg(xr0 + qb + 9) : 0.f;        \
            av[b][s*8+4] = (qb     < NPOS) ? __ldg(xr1 + qb)     : 0.f;        \
            av[b][s*8+5] = (qb + 1 < NPOS) ? __ldg(xr1 + qb + 1) : 0.f;        \
            av[b][s*8+6] = (qb + 8 < NPOS) ? __ldg(xr1 + qb + 8) : 0.f;        \
            av[b][s*8+7] = (qb + 9 < NPOS) ? __ldg(xr1 + qb + 9) : 0.f;        \
        }                                                                      \
    } while (0)

    loadB(sb[0], n0, 0, tid);
    LOAD_A(0, 0);

    #pragma unroll
    for (int c = 0; c < NCHK; c++) {
        const int cur = c & 1;
        if (c + 1 < NCHK) loadB(sb[(c + 1) & 1], n0, (c + 1) * KC, tid);
        if (c + 1 < NCHK) asm volatile("cp.async.wait_group 1;" ::: "memory");
        else              asm volatile("cp.async.wait_group 0;" ::: "memory");
        __syncthreads();

        if (c + 1 < NCHK) LOAD_A((c + 1) & 1, c + 1);   // prefetch next A

        const uint32_t bu = sb[cur];
        #pragma unroll
        for (int s = 0; s < 2; s++) {
            // ---- A fragments from registers (hi/lo split) ----
            uint32_t ah[4], al[4];
            packsplit(av[cur][s*8+0], av[cur][s*8+1], ah[0], al[0]); // (g,   t2)
            packsplit(av[cur][s*8+4], av[cur][s*8+5], ah[1], al[1]); // (g+8, t2)
            packsplit(av[cur][s*8+2], av[cur][s*8+3], ah[2], al[2]); // (g,   t2+8)
            packsplit(av[cur][s*8+6], av[cur][s*8+7], ah[3], al[3]); // (g+8, t2+8)

            // ---- B fragments via ldmatrix ----
            uint32_t bh[4][2], bl[4][2];
            #pragma unroll
            for (int p = 0; p < 2; p++) {
                uint32_t base = bu + bRow + (uint32_t)(p * 16 * (SPITCH * 2))
                              + (uint32_t)(s * 32) + bKof;
                uint32_t rh[4], rl[4];
                ldmx4(rh, base);
                ldmx4(rl, base + 64);
                bh[p*2+0][0] = rh[0]; bh[p*2+0][1] = rh[1];
                bh[p*2+1][0] = rh[2]; bh[p*2+1][1] = rh[3];
                bl[p*2+0][0] = rl[0]; bl[p*2+0][1] = rl[1];
                bl[p*2+1][0] = rl[2]; bl[p*2+1][1] = rl[3];
            }

            // ---- 3 terms, term-major to break same-acc RAW chains ----
            #pragma unroll
            for (int nf = 0; nf < 4; nf++) mma16816(acc[nf], ah, bh[nf]); // hi*hi
            #pragma unroll
            for (int nf = 0; nf < 4; nf++) mma16816(acc[nf], al, bh[nf]); // lo*hi
            #pragma unroll
            for (int nf = 0; nf < 4; nf++) mma16816(acc[nf], ah, bl[nf]); // hi*lo
        }
        __syncthreads();
    }

    // ---- epilogue: direct stores ----
    const int tg = lane & 3;
    const int m  = m0 + wm * 16 + g;
    #pragma unroll
    for (int nf = 0; nf < 4; nf++) {
        const int n = n0 + wn * 32 + nf * 8 + 2 * tg;
        if (m < nplanes) {
            if (n     < NPOS) out[m * NPOS + n]     = acc[nf][0];
            if (n + 1 < NPOS) out[m * NPOS + n + 1] = acc[nf][1];
        }
        if (m + 8 < nplanes) {
            if (n     < NPOS) out[(m + 8) * NPOS + n]     = acc[nf][2];
            if (n + 1 < NPOS) out[(m + 8) * NPOS + n + 1] = acc[nf][3];
        }
    }
}

// ---------------- launch -----------------------------------------------------

extern "C" void kernel_launch(void* const* d_in, const int* in_sizes, int n_in,
                              void* d_out, int out_size)
{
    const float* x      = (const float*)d_in[0];   // [32,64,19,19]
    const float* weight = (const float*)d_in[1];   // [2,18]
    float* out          = (float*)d_out;

    const int nplanes = in_sizes[0] / NPOS;        // 2048

    prep_B<<<(KP * (KP / 2) + 255) / 256, 256>>>(weight);

    dim3 grid((nplanes + MT - 1) / MT, (NPOS + NT - 1) / NT);   // 64 x 6
    gemm_kernel<<<grid, 128>>>(x, out, nplanes);
}